// round 15
// baseline (speedup 1.0000x reference)
#include <cuda_runtime.h>

// LatticeSnake: B=16, N=48, K=7, PAD=3. Reference scatters 48 acids + 47
// inters into a 195^3 lattice (in-order, last-write-wins), extracts a 7^3
// window at each acid's idx2, masks by mask[n].
//
// FINAL — converged at the launch-latency floor; held unchanged since R12.
// Design: all-pairs candidate x window scatter. Window buffer stores only the
// winning candidate index (+1) as 32-bit int; atomicMax over scatter index ==
// last-write-wins ordering (inters after acids, duplicate positions resolved
// exactly as XLA's in-order scatter); value looked up from cand[] at store
// time. WPC=4, 256 threads, grid 12x16 = 192 CTAs (single wave), float2
// store.
//
// Convergence evidence (R3-R14, 11 passing runs, 5 structural designs):
// all pipes <5% of peak (DRAM 0.1%, L1 3.7%, alu 1.8%, issue 11%); bench dur
// uncorrelated with ncu kernel time (4.48-5.28us); THIS binary re-benched 3x
// at 6.62-6.66us (kernel 4.48-4.51us). Residual = launch ramp (~5000 cyc,
// ~2.6us) + per-launch-flushed-L1 cold LDG round + barrier/drain (~4.5us
// kernel total, matching ncu within 1%) + ~2.1us graph-replay overhead in the
// harness timer — all outside the .cu's control. rel_err is exactly 0.0.
//
// Hard-won invariants: mask is int32 (harness materializes JAX bool as 4-byte
// ints — R1). Per-CTA output block is 8-byte aligned only — float2, never
// float4, for output stores (R9). All-pairs spread beats barrier elimination
// (R11: 3-warp atomic serialization > 7-cycle BAR). Pre-zeroing output ahead
// of the loads regresses (R8: extra STG wavefronts queue ahead of the LDG).

#define NACID   48
#define KWIN    7
#define PADW    3
#define CELLS   (KWIN * KWIN * KWIN)   // 343
#define NCAND   (2 * NACID - 1)        // 95
#define WPC     4                      // windows per CTA
#define SLICES  (NACID / WPC)          // 12
#define NTHREADS 256

__global__ __launch_bounds__(NTHREADS)
void lattice_snake_kernel(const float* __restrict__ acids,
                          const int* __restrict__ mask,
                          const int* __restrict__ idx,
                          float* __restrict__ out)
{
    __shared__ __align__(16) int buf[WPC * CELLS];  // winner cand index + 1 (0 = empty)
    __shared__ int4  cand[NCAND];                   // cx, cy, cz, value bits
    __shared__ int   wbase[WPC][3];
    __shared__ float wmask[WPC];

    const int slice = blockIdx.x;      // 0..11
    const int b     = blockIdx.y;      // 0..15
    const int t     = threadIdx.x;

    const int*   idxb = idx   + b * NACID * 3;
    const float* ab   = acids + b * NACID;
    const int*   mb   = mask  + b * NACID;

    // ---- stage 1: zero buffer (int4), build candidates, window bases ----
    {
        int4* bz = (int4*)buf;
        #pragma unroll
        for (int c = t; c < (WPC * CELLS) / 4; c += NTHREADS)
            bz[c] = make_int4(0, 0, 0, 0);
    }

    if (t < NCAND) {
        int cx, cy, cz, live;
        float v;
        if (t < NACID) {
            cx = 2 * idxb[3 * t + 0] + 94 + PADW;
            cy = 2 * idxb[3 * t + 1] + 94 + PADW;
            cz = 2 * idxb[3 * t + 2] + 94 + PADW;
            live = mb[t];
            v = ab[t];
        } else {
            const int j = t - NACID;   // 0..46
            cx = idxb[3 * j + 0] + idxb[3 * (j + 1) + 0] + 94 + PADW;
            cy = idxb[3 * j + 1] + idxb[3 * (j + 1) + 1] + 94 + PADW;
            cz = idxb[3 * j + 2] + idxb[3 * (j + 1) + 2] + 94 + PADW;
            live = mb[j + 1];
            v = ab[j] + ab[j + 1] + 1.0f;
        }
        if (!live) cx = 1 << 20;       // out of unsigned<7 range -> never hits
        cand[t] = make_int4(cx, cy, cz, __float_as_int(v));
    } else if (t >= 128 && t < 128 + WPC) {
        const int w = t - 128;
        const int n = slice * WPC + w;
        wbase[w][0] = 2 * idxb[3 * n + 0] + 94;
        wbase[w][1] = 2 * idxb[3 * n + 1] + 94;
        wbase[w][2] = 2 * idxb[3 * n + 2] + 94;
        wmask[w] = mb[n] ? 1.0f : 0.0f;
    }
    __syncthreads();

    // ---- stage 2: all-pairs candidate x window scatter (380 pairs) ----
    #pragma unroll
    for (int p = t; p < WPC * NCAND; p += NTHREADS) {
        const int w = p / NCAND;
        const int i = p - w * NCAND;
        const int4 c = cand[i];
        const int dx = c.x - wbase[w][0];
        const int dy = c.y - wbase[w][1];
        const int dz = c.z - wbase[w][2];
        if ((unsigned)dx < KWIN && (unsigned)dy < KWIN && (unsigned)dz < KWIN)
            atomicMax(&buf[w * CELLS + dx * 49 + dy * 7 + dz], i + 1);
    }
    __syncthreads();

    // ---- stage 3: float2-vectorized contiguous store (1372 floats) ----
    float2* outb = (float2*)(out + (b * NACID + slice * WPC) * CELLS);
    #pragma unroll
    for (int c2 = t; c2 < (WPC * CELLS) / 2; c2 += NTHREADS) {
        const int c = 2 * c2;
        const int i0 = buf[c];
        const int i1 = buf[c + 1];
        float2 v;
        v.x = i0 ? __int_as_float(cand[i0 - 1].w) * wmask[c / CELLS] : 0.0f;
        v.y = i1 ? __int_as_float(cand[i1 - 1].w) * wmask[(c + 1) / CELLS] : 0.0f;
        outb[c2] = v;
    }
}

extern "C" void kernel_launch(void* const* d_in, const int* in_sizes, int n_in,
                              void* d_out, int out_size)
{
    const float* acids = (const float*)d_in[0];   // (B, N) float32
    const int*   mask  = (const int*)d_in[1];     // (B, N) bool -> int32
    const int*   idx   = (const int*)d_in[2];     // (B, N, 3) int32
    float*       out   = (float*)d_out;           // (B, N, 7,7,7, 1) float32

    dim3 grid(SLICES, 16);
    lattice_snake_kernel<<<grid, NTHREADS>>>(acids, mask, idx, out);
}

// round 16
// speedup vs baseline: 1.0386x; 1.0386x over previous
#include <cuda_runtime.h>

// LatticeSnake: B=16, N=48, K=7, PAD=3. Reference scatters 48 acids + 47
// inters into a 195^3 lattice (in-order, last-write-wins), extracts a 7^3
// window at each acid's idx2, masks by mask[n].
//
// TERMINAL FORM — converged at the launch-latency floor (held since R12; this
// round adds only __stcs streaming-store hints on the write-once output).
// Design: all-pairs candidate x window scatter. Window buffer stores the
// winning candidate index (+1) as 32-bit int; atomicMax over scatter index ==
// last-write-wins ordering (inters after acids, duplicates resolved exactly
// as XLA's in-order scatter); value looked up from cand[] at store time.
// WPC=4, 256 threads, grid 12x16 = 192 CTAs (single wave), float2 store.
//
// Convergence evidence (R3-R15, 12 passing runs, 5 structural designs):
// all pipes <5% of peak; bench dur uncorrelated with ncu kernel time; the
// IDENTICAL binary benched 4x at 6.62-6.88us (kernel 4.48-4.74us) — one
// distribution containing every result since R3. Residual = launch ramp
// (~5000 cyc) + per-launch-flushed-L1 cold LDG round + barriers/drain
// (~4.5us kernel) + ~2.1us graph-replay overhead in the harness timer.
// rel_err is exactly 0.0.
//
// Hard-won invariants: mask is int32 (harness materializes JAX bool as 4-byte
// ints — R1). Per-CTA output block is 8-byte aligned only — float2, never
// float4 (R9). All-pairs spread beats barrier elimination (R11). Pre-zeroing
// output ahead of the loads regresses (R8).

#define NACID   48
#define KWIN    7
#define PADW    3
#define CELLS   (KWIN * KWIN * KWIN)   // 343
#define NCAND   (2 * NACID - 1)        // 95
#define WPC     4                      // windows per CTA
#define SLICES  (NACID / WPC)          // 12
#define NTHREADS 256

__global__ __launch_bounds__(NTHREADS)
void lattice_snake_kernel(const float* __restrict__ acids,
                          const int* __restrict__ mask,
                          const int* __restrict__ idx,
                          float* __restrict__ out)
{
    __shared__ __align__(16) int buf[WPC * CELLS];  // winner cand index + 1 (0 = empty)
    __shared__ int4  cand[NCAND];                   // cx, cy, cz, value bits
    __shared__ int   wbase[WPC][3];
    __shared__ float wmask[WPC];

    const int slice = blockIdx.x;      // 0..11
    const int b     = blockIdx.y;      // 0..15
    const int t     = threadIdx.x;

    const int*   idxb = idx   + b * NACID * 3;
    const float* ab   = acids + b * NACID;
    const int*   mb   = mask  + b * NACID;

    // ---- stage 1: zero buffer (int4), build candidates, window bases ----
    {
        int4* bz = (int4*)buf;
        #pragma unroll
        for (int c = t; c < (WPC * CELLS) / 4; c += NTHREADS)
            bz[c] = make_int4(0, 0, 0, 0);
    }

    if (t < NCAND) {
        int cx, cy, cz, live;
        float v;
        if (t < NACID) {
            cx = 2 * idxb[3 * t + 0] + 94 + PADW;
            cy = 2 * idxb[3 * t + 1] + 94 + PADW;
            cz = 2 * idxb[3 * t + 2] + 94 + PADW;
            live = mb[t];
            v = ab[t];
        } else {
            const int j = t - NACID;   // 0..46
            cx = idxb[3 * j + 0] + idxb[3 * (j + 1) + 0] + 94 + PADW;
            cy = idxb[3 * j + 1] + idxb[3 * (j + 1) + 1] + 94 + PADW;
            cz = idxb[3 * j + 2] + idxb[3 * (j + 1) + 2] + 94 + PADW;
            live = mb[j + 1];
            v = ab[j] + ab[j + 1] + 1.0f;
        }
        if (!live) cx = 1 << 20;       // out of unsigned<7 range -> never hits
        cand[t] = make_int4(cx, cy, cz, __float_as_int(v));
    } else if (t >= 128 && t < 128 + WPC) {
        const int w = t - 128;
        const int n = slice * WPC + w;
        wbase[w][0] = 2 * idxb[3 * n + 0] + 94;
        wbase[w][1] = 2 * idxb[3 * n + 1] + 94;
        wbase[w][2] = 2 * idxb[3 * n + 2] + 94;
        wmask[w] = mb[n] ? 1.0f : 0.0f;
    }
    __syncthreads();

    // ---- stage 2: all-pairs candidate x window scatter (380 pairs) ----
    #pragma unroll
    for (int p = t; p < WPC * NCAND; p += NTHREADS) {
        const int w = p / NCAND;
        const int i = p - w * NCAND;
        const int4 c = cand[i];
        const int dx = c.x - wbase[w][0];
        const int dy = c.y - wbase[w][1];
        const int dz = c.z - wbase[w][2];
        if ((unsigned)dx < KWIN && (unsigned)dy < KWIN && (unsigned)dz < KWIN)
            atomicMax(&buf[w * CELLS + dx * 49 + dy * 7 + dz], i + 1);
    }
    __syncthreads();

    // ---- stage 3: float2 streaming store (write-once output, never re-read) ----
    float2* outb = (float2*)(out + (b * NACID + slice * WPC) * CELLS);
    #pragma unroll
    for (int c2 = t; c2 < (WPC * CELLS) / 2; c2 += NTHREADS) {
        const int c = 2 * c2;
        const int i0 = buf[c];
        const int i1 = buf[c + 1];
        float2 v;
        v.x = i0 ? __int_as_float(cand[i0 - 1].w) * wmask[c / CELLS] : 0.0f;
        v.y = i1 ? __int_as_float(cand[i1 - 1].w) * wmask[(c + 1) / CELLS] : 0.0f;
        __stcs(&outb[c2], v);
    }
}

extern "C" void kernel_launch(void* const* d_in, const int* in_sizes, int n_in,
                              void* d_out, int out_size)
{
    const float* acids = (const float*)d_in[0];   // (B, N) float32
    const int*   mask  = (const int*)d_in[1];     // (B, N) bool -> int32
    const int*   idx   = (const int*)d_in[2];     // (B, N, 3) int32
    float*       out   = (float*)d_out;           // (B, N, 7,7,7, 1) float32

    dim3 grid(SLICES, 16);
    lattice_snake_kernel<<<grid, NTHREADS>>>(acids, mask, idx, out);
}